// round 15
// baseline (speedup 1.0000x reference)
#include <cuda_runtime.h>
#include <math.h>
#include <stdint.h>

#define D_MODEL 1024
#define NH      16
#define HD      64
#define B_      2
#define T_      2048
#define BT      4096
#define BH      32

// ------------------------- device scratch (no allocs) ----------------------
__device__ float g_x  [BT * D_MODEL];      // x, tf32-rounded
__device__ float g_q  [BH * T_ * HD];      // [bh][t][dd]   (tf32)
__device__ float g_k  [BH * T_ * HD];      // [bh][s][dd]   (tf32)
__device__ float g_v  [BH * T_ * HD];      // [bh][t][dd]   (exact)
__device__ float g_vt [BH * HD * T_];      // [bh][dd][t]   (tf32)
__device__ float g_ao [BT * D_MODEL];      // [b*t][D]      (tf32)
__device__ float g_wt [3 * D_MODEL * D_MODEL];   // Wqkv^T (tf32)
__device__ float g_wot[D_MODEL * D_MODEL];       // Wo^T   (tf32)
__device__ float g_rowsum[BH * T_];

// ------------------------------ helpers ------------------------------------
__device__ __forceinline__ uint32_t s2u(const void* p) {
    return (uint32_t)__cvta_generic_to_shared(p);
}
__device__ __forceinline__ void cpa16(uint32_t d, const void* g) {
    asm volatile("cp.async.cg.shared.global [%0], [%1], 16;" :: "r"(d), "l"(g));
}
__device__ __forceinline__ void cpcommit() { asm volatile("cp.async.commit_group;"); }
template <int N> __device__ __forceinline__ void cpwait() {
    asm volatile("cp.async.wait_group %0;" :: "n"(N));
}
__device__ __forceinline__ float f2tf(float f) {
    uint32_t r; asm("cvt.rna.tf32.f32 %0, %1;" : "=r"(r) : "f"(f));
    return __uint_as_float(r);
}
__device__ __forceinline__ void mma8(float* c, const uint32_t* a, const uint32_t* b) {
    asm volatile("mma.sync.aligned.m16n8k8.row.col.f32.tf32.tf32.f32 "
        "{%0,%1,%2,%3}, {%4,%5,%6,%7}, {%8,%9}, {%0,%1,%2,%3};"
        : "+f"(c[0]), "+f"(c[1]), "+f"(c[2]), "+f"(c[3])
        : "r"(a[0]), "r"(a[1]), "r"(a[2]), "r"(a[3]), "r"(b[0]), "r"(b[1]));
}
__device__ __forceinline__ void ldsm4(uint32_t& r0, uint32_t& r1,
                                      uint32_t& r2, uint32_t& r3, uint32_t addr) {
    asm volatile("ldmatrix.sync.aligned.m8n8.x4.shared.b16 {%0,%1,%2,%3}, [%4];"
        : "=r"(r0), "=r"(r1), "=r"(r2), "=r"(r3) : "r"(addr));
}

// ======================= prep kernels =======================================
__global__ void cvt_x(const float* __restrict__ x) {
    size_t i = ((size_t)blockIdx.x * 256 + threadIdx.x) * 4;
    float4 v = *(const float4*)&x[i];
    v.x = f2tf(v.x); v.y = f2tf(v.y); v.z = f2tf(v.z); v.w = f2tf(v.w);
    *(float4*)&g_x[i] = v;
    if (blockIdx.x < 256) g_rowsum[blockIdx.x * 256 + threadIdx.x] = 0.f;
}

__global__ void transpose_w2(const float* __restrict__ Wqkv,
                             const float* __restrict__ Wo,
                             float* __restrict__ outq, float* __restrict__ outo) {
    __shared__ float tb[32][33];
    int z = blockIdx.z;
    const float* in; float* out; int R = 1024, C;
    if (z == 0) { in = Wqkv; out = outq; C = 3072; }
    else        { in = Wo;   out = outo; C = 1024; }
    int bx = blockIdx.x * 32, by = blockIdx.y * 32;
    if (bx >= C) return;
    int x = bx + threadIdx.x;
    #pragma unroll
    for (int i = threadIdx.y; i < 32; i += 8)
        tb[i][threadIdx.x] = in[(size_t)(by + i) * C + x];
    __syncthreads();
    int x2 = by + threadIdx.x;
    #pragma unroll
    for (int i = threadIdx.y; i < 32; i += 8)
        out[(size_t)(bx + i) * R + x2] = f2tf(tb[threadIdx.x][i]);
}

__global__ void transpose_v() {
    __shared__ float tb[32][33];
    int bh = blockIdx.z;
    const float* in = g_v + (size_t)bh * T_ * HD;
    float* out = g_vt + (size_t)bh * HD * T_;
    int bx = blockIdx.x * 32, by = blockIdx.y * 32;
    int x = bx + threadIdx.x;
    #pragma unroll
    for (int i = threadIdx.y; i < 32; i += 8)
        tb[i][threadIdx.x] = in[(size_t)(by + i) * HD + x];
    __syncthreads();
    int x2 = by + threadIdx.x;
    #pragma unroll
    for (int i = threadIdx.y; i < 32; i += 8)
        out[(size_t)(bx + i) * T_ + x2] = f2tf(tb[threadIdx.x][i]);
}

// ======================= big projection GEMM (R14, unchanged) ===============
#define GBS 36
template <int MODE>
__global__ void __launch_bounds__(256, 2)
gemm_big(const float* __restrict__ A, const float* __restrict__ Bt,
         const float* __restrict__ bias, float* __restrict__ Cout) {
    extern __shared__ float sm[];
    float (*As)[128][GBS] = (float(*)[128][GBS])sm;
    float (*Bs)[128][GBS] = (float(*)[128][GBS])(sm + 3 * 128 * GBS);

    int tid = threadIdx.x, wid = tid >> 5, lane = tid & 31;
    int gr = lane >> 2, tq = lane & 3;
    int warpm = wid & 3, warpn = wid >> 2;
    int row0 = blockIdx.y * 128, col0 = blockIdx.x * 128;

    int g8 = lane >> 3, lr = lane & 7;
    int aro = (g8 & 1) * 8 + lr, aco = (g8 >> 1) * 4;
    int bro = (g8 >> 1) * 8 + lr, bco = (g8 & 1) * 4;

    float acc[2][8][4];
    #pragma unroll
    for (int i = 0; i < 2; i++)
        #pragma unroll
        for (int j = 0; j < 8; j++)
            #pragma unroll
            for (int q = 0; q < 4; q++) acc[i][j][q] = 0.f;

    auto load_stage = [&](int c) {
        int s = c % 3;
        #pragma unroll
        for (int p = 0; p < 4; p++) {
            int idx = tid + p * 256;
            int r = idx >> 3, c16 = idx & 7;
            cpa16(s2u(&As[s][r][c16 * 4]), &A[(size_t)(row0 + r) * 1024 + c * 32 + c16 * 4]);
            cpa16(s2u(&Bs[s][r][c16 * 4]), &Bt[(size_t)(col0 + r) * 1024 + c * 32 + c16 * 4]);
        }
        cpcommit();
    };

    auto mma_half = [&](int s, int k8base) {
        #pragma unroll
        for (int k8 = 0; k8 < 16; k8 += 8) {
            int kk = k8base + k8;
            uint32_t a[2][4];
            #pragma unroll
            for (int i = 0; i < 2; i++)
                ldsm4(a[i][0], a[i][1], a[i][2], a[i][3],
                      s2u(&As[s][warpm * 32 + i * 16 + aro][kk + aco]));
            #pragma unroll
            for (int jp = 0; jp < 4; jp++) {
                uint32_t b0, b1, b2, b3;
                ldsm4(b0, b1, b2, b3,
                      s2u(&Bs[s][warpn * 64 + jp * 16 + bro][kk + bco]));
                uint32_t bj0[2] = {b0, b1}, bj1[2] = {b2, b3};
                #pragma unroll
                for (int i = 0; i < 2; i++) {
                    mma8(acc[i][jp * 2 + 0], a[i], bj0);
                    mma8(acc[i][jp * 2 + 1], a[i], bj1);
                }
            }
        }
    };

    load_stage(0); load_stage(1);

    for (int c = 0; c < 32; c++) {
        int s = c % 3;
        if (c < 31) cpwait<1>(); else cpwait<0>();
        __syncthreads();

        mma_half(s, 0);
        if (c + 2 < 32) load_stage(c + 2);
        mma_half(s, 16);
    }

    #pragma unroll
    for (int i = 0; i < 2; i++) {
        #pragma unroll
        for (int half = 0; half < 2; half++) {
            int m = row0 + warpm * 32 + i * 16 + gr + half * 8;
            #pragma unroll
            for (int j = 0; j < 8; j++) {
                int col = col0 + warpn * 64 + j * 8 + 2 * tq;
                float v0 = acc[i][j][half * 2 + 0] + __ldg(&bias[col]);
                float v1 = acc[i][j][half * 2 + 1] + __ldg(&bias[col + 1]);
                if (MODE == 1) {
                    *(float2*)&Cout[(size_t)m * 1024 + col] = make_float2(v0, v1);
                } else {
                    int which = col >> 10;
                    int d = col & 1023, h = d >> 6, dd = d & 63;
                    int b = m >> 11, t = m & 2047;
                    if (which != 2) { v0 = f2tf(v0); v1 = f2tf(v1); }
                    float* dst = (which == 0) ? g_q : (which == 1) ? g_k : g_v;
                    *(float2*)&dst[((size_t)(b * NH + h) * T_ + t) * HD + dd] =
                        make_float2(v0, v1);
                }
            }
        }
    }
}

// ======================= kernel A: rowsums only (R14, unchanged) ============
__global__ void __launch_bounds__(256, 2) attn_rowsum() {
    extern __shared__ float sm[];
    float* Qs = sm;                 // [128][68]
    float* Ks = sm + 128 * 68;      // [2][128][68]

    int tid = threadIdx.x, wid = tid >> 5, lane = tid & 31;
    int gr = lane >> 2, tq = lane & 3;
    int warpm = wid & 3, warpn = wid >> 2;
    int r0 = blockIdx.x * 128, bh = blockIdx.y;

    int g8 = lane >> 3, lr = lane & 7;
    int aro = (g8 & 1) * 8 + lr, aco = (g8 >> 1) * 4;
    int bro = (g8 >> 1) * 8 + lr, bco = (g8 & 1) * 4;

    const float* qh = g_q + ((size_t)bh * T_ + r0) * HD;
    const float* kh = g_k + (size_t)bh * T_ * HD;

    auto loadK = [&](int c) {
        float* dst = Ks + (size_t)(c & 1) * 128 * 68;
        #pragma unroll
        for (int p = 0; p < 8; p++) {
            int idx = tid + p * 256;
            int r = idx >> 4, c4 = idx & 15;
            cpa16(s2u(&dst[r * 68 + c4 * 4]), kh + (size_t)(c * 128 + r) * HD + c4 * 4);
        }
        cpcommit();
    };

    #pragma unroll
    for (int p = 0; p < 8; p++) {
        int idx = tid + p * 256;
        int r = idx >> 4, c4 = idx & 15;
        cpa16(s2u(&Qs[r * 68 + c4 * 4]), qh + (size_t)r * HD + c4 * 4);
    }
    {
        float* dst = Ks;
        #pragma unroll
        for (int p = 0; p < 8; p++) {
            int idx = tid + p * 256;
            int r = idx >> 4, c4 = idx & 15;
            cpa16(s2u(&dst[r * 68 + c4 * 4]), kh + (size_t)r * HD + c4 * 4);
        }
    }
    cpcommit();
    loadK(1);

    float sums[2][2] = {{0.f, 0.f}, {0.f, 0.f}};

    for (int c = 0; c < 16; c++) {
        if (c < 15) cpwait<1>(); else cpwait<0>();
        __syncthreads();
        const float* Kb = Ks + (size_t)(c & 1) * 128 * 68;

        float acc[2][8][4];
        #pragma unroll
        for (int i = 0; i < 2; i++)
            #pragma unroll
            for (int j = 0; j < 8; j++)
                #pragma unroll
                for (int q = 0; q < 4; q++) acc[i][j][q] = 0.f;

        #pragma unroll
        for (int k8 = 0; k8 < 64; k8 += 8) {
            uint32_t a[2][4];
            #pragma unroll
            for (int i = 0; i < 2; i++)
                ldsm4(a[i][0], a[i][1], a[i][2], a[i][3],
                      s2u(&Qs[(warpm * 32 + i * 16 + aro) * 68 + k8 + aco]));
            #pragma unroll
            for (int jp = 0; jp < 4; jp++) {
                uint32_t b0, b1, b2, b3;
                ldsm4(b0, b1, b2, b3,
                      s2u(&Kb[(warpn * 64 + jp * 16 + bro) * 68 + k8 + bco]));
                uint32_t bj0[2] = {b0, b1}, bj1[2] = {b2, b3};
                #pragma unroll
                for (int i = 0; i < 2; i++) {
                    mma8(acc[i][jp * 2 + 0], a[i], bj0);
                    mma8(acc[i][jp * 2 + 1], a[i], bj1);
                }
            }
        }

        #pragma unroll
        for (int i = 0; i < 2; i++)
            #pragma unroll
            for (int half = 0; half < 2; half++) {
                float s = 0.f;
                #pragma unroll
                for (int j = 0; j < 8; j++) {
                    s += __expf(0.125f * acc[i][j][half * 2 + 0]);
                    s += __expf(0.125f * acc[i][j][half * 2 + 1]);
                }
                sums[i][half] += s;
            }

        __syncthreads();
        if (c + 2 < 16) loadK(c + 2);
    }

    #pragma unroll
    for (int i = 0; i < 2; i++)
        #pragma unroll
        for (int half = 0; half < 2; half++) {
            float s = sums[i][half];
            s += __shfl_xor_sync(0xffffffffu, s, 1);
            s += __shfl_xor_sync(0xffffffffu, s, 2);
            if (tq == 0) {
                int r = r0 + warpm * 32 + i * 16 + gr + half * 8;
                atomicAdd(&g_rowsum[(size_t)bh * T_ + r], s);
            }
        }
}

// ============ kernel B: fused W-write + O, 512 threads (16 warps) ===========
#define ESS 132
#define FB_QS   0
#define FB_KS   (128 * 68)
#define FB_ES   (FB_KS + 2 * 128 * 68)
#define FB_VS   (FB_ES + 128 * ESS)
#define FB_INV  (FB_VS + 64 * 132)
#define FB_FLTS (FB_INV + 128)

__global__ void __launch_bounds__(512, 1) attn_fused(float* __restrict__ wts) {
    extern __shared__ float sm[];
    float* Qs  = sm + FB_QS;
    float* Ks  = sm + FB_KS;
    float* Es  = sm + FB_ES;
    float* Vs  = sm + FB_VS;
    float* inv = sm + FB_INV;

    int tid = threadIdx.x, wid = tid >> 5, lane = tid & 31;
    int gr = lane >> 2, tq = lane & 3;
    int warpm = wid & 3, warpn = wid >> 2;   // 4 x 4 warps
    int r0 = blockIdx.x * 128, bh = blockIdx.y;

    int g8 = lane >> 3, lr = lane & 7;
    int aro = (g8 & 1) * 8 + lr, aco = (g8 >> 1) * 4;
    int bro = (g8 >> 1) * 8 + lr, bco = (g8 & 1) * 4;

    const float* qh  = g_q  + ((size_t)bh * T_ + r0) * HD;
    const float* kh  = g_k  + (size_t)bh * T_ * HD;
    const float* vtb = g_vt + (size_t)bh * HD * T_;
    float* wbase = wts + ((size_t)bh * T_ + r0) * T_;

    if (tid < 128) inv[tid] = 1.f / g_rowsum[(size_t)bh * T_ + r0 + tid];

    auto loadK = [&](int c) {
        float* dst = Ks + (size_t)(c & 1) * 128 * 68;
        #pragma unroll
        for (int p = 0; p < 4; p++) {
            int idx = tid + p * 512;
            int r = idx >> 4, c4 = idx & 15;
            cpa16(s2u(&dst[r * 68 + c4 * 4]), kh + (size_t)(c * 128 + r) * HD + c4 * 4);
        }
        cpcommit();
    };
    auto loadV = [&](int c) {
        #pragma unroll
        for (int p = 0; p < 4; p++) {
            int idx = tid + p * 512;
            int r = idx >> 5, c4 = idx & 31;
            cpa16(s2u(&Vs[r * 132 + c4 * 4]), vtb + (size_t)r * T_ + c * 128 + c4 * 4);
        }
        cpcommit();
    };

    // prologue: Q + K0 (one group), then nothing else outstanding
    #pragma unroll
    for (int p = 0; p < 4; p++) {
        int idx = tid + p * 512;
        int r = idx >> 4, c4 = idx & 15;
        cpa16(s2u(&Qs[r * 68 + c4 * 4]), qh + (size_t)r * HD + c4 * 4);
    }
    {
        float* dst = Ks;
        #pragma unroll
        for (int p = 0; p < 4; p++) {
            int idx = tid + p * 512;
            int r = idx >> 4, c4 = idx & 15;
            cpa16(s2u(&dst[r * 68 + c4 * 4]), kh + (size_t)r * HD + c4 * 4);
        }
    }
    cpcommit();

    float acco[2][2][4];
    #pragma unroll
    for (int i = 0; i < 2; i++)
        #pragma unroll
        for (int j = 0; j < 2; j++)
            #pragma unroll
            for (int q = 0; q < 4; q++) acco[i][j][q] = 0.f;

    for (int c = 0; c < 16; c++) {
        cpwait<0>();
        __syncthreads();             // Ks[c] visible; Es/Vs free; inv ready
        loadV(c);
        if (c < 15) loadK(c + 1);

        const float* Kb = Ks + (size_t)(c & 1) * 128 * 68;

        // ---- QK^T: warp tile 32 rows x 32 keys ----
        float acc[2][4][4];
        #pragma unroll
        for (int i = 0; i < 2; i++)
            #pragma unroll
            for (int j = 0; j < 4; j++)
                #pragma unroll
                for (int q = 0; q < 4; q++) acc[i][j][q] = 0.f;

        #pragma unroll
        for (int k8 = 0; k8 < 64; k8 += 8) {
            uint32_t a[2][4];
            #pragma unroll
            for (int i = 0; i < 2; i++)
                ldsm4(a[i][0], a[i][1], a[i][2], a[i][3],
                      s2u(&Qs[(warpm * 32 + i * 16 + aro) * 68 + k8 + aco]));
            #pragma unroll
            for (int jp = 0; jp < 2; jp++) {
                uint32_t b0, b1, b2, b3;
                ldsm4(b0, b1, b2, b3,
                      s2u(&Kb[(warpn * 32 + jp * 16 + bro) * 68 + k8 + bco]));
                uint32_t bj0[2] = {b0, b1}, bj1[2] = {b2, b3};
                #pragma unroll
                for (int i = 0; i < 2; i++) {
                    mma8(acc[i][jp * 2 + 0], a[i], bj0);
                    mma8(acc[i][jp * 2 + 1], a[i], bj1);
                }
            }
        }

        // ---- w = exp*inv -> Es ----
        #pragma unroll
        for (int i = 0; i < 2; i++) {
            #pragma unroll
            for (int half = 0; half < 2; half++) {
                int lrw = warpm * 32 + i * 16 + gr + half * 8;
                float iv = inv[lrw];
                #pragma unroll
                for (int j = 0; j < 4; j++) {
                    int col = warpn * 32 + j * 8 + 2 * tq;
                    float w0 = __expf(0.125f * acc[i][j][half * 2 + 0]) * iv;
                    float w1 = __expf(0.125f * acc[i][j][half * 2 + 1]) * iv;
                    *(float2*)&Es[lrw * ESS + col] = make_float2(w0, w1);
                }
            }
        }

        if (c < 15) cpwait<1>(); else cpwait<0>();   // V[c] arrived
        __syncthreads();                              // Es + Vs visible

        // ---- coalesced W store: 8 rows per warp ----
        #pragma unroll
        for (int rr = 0; rr < 8; rr++) {
            int row = wid * 8 + rr;
            float4 v = *(float4*)&Es[row * ESS + lane * 4];
            *(float4*)&wbase[(size_t)row * T_ + c * 128 + lane * 4] = v;
        }

        // ---- O += Es @ V: warp tile 32 rows x 16 dd ----
        #pragma unroll
        for (int k8 = 0; k8 < 128; k8 += 8) {
            uint32_t a[2][4];
            #pragma unroll
            for (int i = 0; i < 2; i++)
                ldsm4(a[i][0], a[i][1], a[i][2], a[i][3],
                      s2u(&Es[(warpm * 32 + i * 16 + aro) * ESS + k8 + aco]));
            uint32_t b0, b1, b2, b3;
            ldsm4(b0, b1, b2, b3,
                  s2u(&Vs[(warpn * 16 + bro) * 132 + k8 + bco]));
            uint32_t bj0[2] = {b0, b1}, bj1[2] = {b2, b3};
            #pragma unroll
            for (int i = 0; i < 2; i++) {
                mma8(acco[i][0], a[i], bj0);
                mma8(acco[i][1], a[i], bj1);
            }
        }
    }

    // ---- epilogue: O -> g_ao (tf32) ----
    int b = bh >> 4, h = bh & 15;
    #pragma unroll
    for (int i = 0; i < 2; i++) {
        #pragma unroll
        for (int half = 0; half < 2; half++) {
            int t = r0 + warpm * 32 + i * 16 + gr + half * 8;
            float* orow = g_ao + (size_t)(b * T_ + t) * D_MODEL + h * HD;
            #pragma unroll
            for (int j = 0; j < 2; j++) {
                int dd = warpn * 16 + j * 8 + 2 * tq;
                *(float2*)&orow[dd] = make_float2(
                    f2tf(acco[i][j][half * 2 + 0]), f2tf(acco[i][j][half * 2 + 1]));
            }
        }
    }
}

// ===========================================================================
extern "C" void kernel_launch(void* const* d_in, const int* in_sizes, int n_in,
                              void* d_out, int out_size) {
    const float* x    = (const float*)d_in[0];
    const float* Wqkv = (const float*)d_in[1];
    const float* bqkv = (const float*)d_in[2];
    const float* Wo   = (const float*)d_in[3];
    const float* bo   = (const float*)d_in[4];

    float* y   = (float*)d_out;                         // [B,T,D]
    float* wts = (float*)d_out + (size_t)BT * D_MODEL;  // [B,H,T,T]

    const int GB_SMEM = 2 * 3 * 128 * GBS * 4;          // 110592
    const int RS_SMEM = 3 * 128 * 68 * 4;               // 104448
    const int FB_SMEM = FB_FLTS * 4;
    cudaFuncSetAttribute(gemm_big<0>, cudaFuncAttributeMaxDynamicSharedMemorySize, GB_SMEM);
    cudaFuncSetAttribute(gemm_big<1>, cudaFuncAttributeMaxDynamicSharedMemorySize, GB_SMEM);
    cudaFuncSetAttribute(attn_rowsum, cudaFuncAttributeMaxDynamicSharedMemorySize, RS_SMEM);
    cudaFuncSetAttribute(attn_fused,  cudaFuncAttributeMaxDynamicSharedMemorySize, FB_SMEM);

    float *wt_p = nullptr, *wot_p = nullptr, *ao_p = nullptr, *x_p = nullptr;
    cudaGetSymbolAddress((void**)&wt_p,  g_wt);
    cudaGetSymbolAddress((void**)&wot_p, g_wot);
    cudaGetSymbolAddress((void**)&ao_p,  g_ao);
    cudaGetSymbolAddress((void**)&x_p,   g_x);

    cvt_x<<<BT * D_MODEL / 1024, 256>>>(x);   // also zeroes g_rowsum
    transpose_w2<<<dim3(96, 32, 2), dim3(32, 8)>>>(Wqkv, Wo, wt_p, wot_p);

    gemm_big<0><<<dim3(24, 32), 256, GB_SMEM>>>(x_p, wt_p, bqkv, nullptr);
    transpose_v<<<dim3(2, 64, 32), dim3(32, 8)>>>();

    attn_rowsum<<<dim3(16, 32), 256, RS_SMEM>>>();
    attn_fused<<<dim3(16, 32), 512, FB_SMEM>>>(wts);

    gemm_big<1><<<dim3(8, 32), 256, GB_SMEM>>>(ao_p, wot_p, bo, y);
}

// round 16
// speedup vs baseline: 1.0523x; 1.0523x over previous
#include <cuda_runtime.h>
#include <math.h>
#include <stdint.h>

#define D_MODEL 1024
#define NH      16
#define HD      64
#define B_      2
#define T_      2048
#define BT      4096
#define BH      32

// ------------------------- device scratch (no allocs) ----------------------
__device__ float g_q  [BH * T_ * HD];      // [bh][t][dd]   (tf32)
__device__ float g_k  [BH * T_ * HD];      // [bh][s][dd]   (tf32)
__device__ float g_v  [BH * T_ * HD];      // [bh][t][dd]   (exact)
__device__ float g_vt [BH * HD * T_];      // [bh][dd][t]   (tf32)
__device__ float g_ao [BT * D_MODEL];      // [b*t][D]      (tf32)
__device__ float g_wt [3 * D_MODEL * D_MODEL];   // Wqkv^T (tf32)
__device__ float g_wot[D_MODEL * D_MODEL];       // Wo^T   (tf32)
__device__ float g_rowsum[BH * T_];

// ------------------------------ helpers ------------------------------------
__device__ __forceinline__ uint32_t s2u(const void* p) {
    return (uint32_t)__cvta_generic_to_shared(p);
}
__device__ __forceinline__ void cpa16(uint32_t d, const void* g) {
    asm volatile("cp.async.cg.shared.global [%0], [%1], 16;" :: "r"(d), "l"(g));
}
__device__ __forceinline__ void cpcommit() { asm volatile("cp.async.commit_group;"); }
template <int N> __device__ __forceinline__ void cpwait() {
    asm volatile("cp.async.wait_group %0;" :: "n"(N));
}
__device__ __forceinline__ float f2tf(float f) {
    uint32_t r; asm("cvt.rna.tf32.f32 %0, %1;" : "=r"(r) : "f"(f));
    return __uint_as_float(r);
}
__device__ __forceinline__ void mma8(float* c, const uint32_t* a, const uint32_t* b) {
    asm volatile("mma.sync.aligned.m16n8k8.row.col.f32.tf32.tf32.f32 "
        "{%0,%1,%2,%3}, {%4,%5,%6,%7}, {%8,%9}, {%0,%1,%2,%3};"
        : "+f"(c[0]), "+f"(c[1]), "+f"(c[2]), "+f"(c[3])
        : "r"(a[0]), "r"(a[1]), "r"(a[2]), "r"(a[3]), "r"(b[0]), "r"(b[1]));
}
__device__ __forceinline__ void ldsm4(uint32_t& r0, uint32_t& r1,
                                      uint32_t& r2, uint32_t& r3, uint32_t addr) {
    asm volatile("ldmatrix.sync.aligned.m8n8.x4.shared.b16 {%0,%1,%2,%3}, [%4];"
        : "=r"(r0), "=r"(r1), "=r"(r2), "=r"(r3) : "r"(addr));
}

// ======================= prep kernels =======================================
// combined transpose: z=0 -> Wqkv (1024x3072); z=1 -> Wo (1024x1024).
// z=1 blocks with bx >= 1024 instead zero g_rowsum (64 blocks x 1024 floats).
__global__ void transpose_w2(const float* __restrict__ Wqkv,
                             const float* __restrict__ Wo,
                             float* __restrict__ outq, float* __restrict__ outo) {
    __shared__ float tb[32][33];
    int z = blockIdx.z;
    const float* in; float* out; int R = 1024, C;
    if (z == 0) { in = Wqkv; out = outq; C = 3072; }
    else        { in = Wo;   out = outo; C = 1024; }
    int bx = blockIdx.x * 32, by = blockIdx.y * 32;
    if (bx >= C) {
        if (z == 1) {
            // blocks x=32..95, y=0..31 -> zero g_rowsum (65536 floats)
            int bid = (blockIdx.x - 32) + 64 * 0;   // x in [32,96)
            if (blockIdx.y < 4) {
                size_t base = ((size_t)(blockIdx.y * 64 + bid) * 256 + threadIdx.y * 32 + threadIdx.x);
                if (base < (size_t)BH * T_) g_rowsum[base] = 0.f;
            }
        }
        return;
    }
    int x = bx + threadIdx.x;
    #pragma unroll
    for (int i = threadIdx.y; i < 32; i += 8)
        tb[i][threadIdx.x] = in[(size_t)(by + i) * C + x];
    __syncthreads();
    int x2 = by + threadIdx.x;
    #pragma unroll
    for (int i = threadIdx.y; i < 32; i += 8)
        out[(size_t)(bx + i) * R + x2] = f2tf(tb[threadIdx.x][i]);
}

__global__ void zero_rowsum2() {   // safety net: cheap, guaranteed coverage
    g_rowsum[blockIdx.x * 256 + threadIdx.x] = 0.f;
}

__global__ void transpose_v() {
    __shared__ float tb[32][33];
    int bh = blockIdx.z;
    const float* in = g_v + (size_t)bh * T_ * HD;
    float* out = g_vt + (size_t)bh * HD * T_;
    int bx = blockIdx.x * 32, by = blockIdx.y * 32;
    int x = bx + threadIdx.x;
    #pragma unroll
    for (int i = threadIdx.y; i < 32; i += 8)
        tb[i][threadIdx.x] = in[(size_t)(by + i) * HD + x];
    __syncthreads();
    int x2 = by + threadIdx.x;
    #pragma unroll
    for (int i = threadIdx.y; i < 32; i += 8)
        out[(size_t)(bx + i) * T_ + x2] = f2tf(tb[threadIdx.x][i]);
}

// ======================= big projection GEMM (R14) ===========================
#define GBS 36
template <int MODE>
__global__ void __launch_bounds__(256, 2)
gemm_big(const float* __restrict__ A, const float* __restrict__ Bt,
         const float* __restrict__ bias, float* __restrict__ Cout) {
    extern __shared__ float sm[];
    float (*As)[128][GBS] = (float(*)[128][GBS])sm;
    float (*Bs)[128][GBS] = (float(*)[128][GBS])(sm + 3 * 128 * GBS);

    int tid = threadIdx.x, wid = tid >> 5, lane = tid & 31;
    int gr = lane >> 2, tq = lane & 3;
    int warpm = wid & 3, warpn = wid >> 2;
    int row0 = blockIdx.y * 128, col0 = blockIdx.x * 128;

    int g8 = lane >> 3, lr = lane & 7;
    int aro = (g8 & 1) * 8 + lr, aco = (g8 >> 1) * 4;
    int bro = (g8 >> 1) * 8 + lr, bco = (g8 & 1) * 4;

    float acc[2][8][4];
    #pragma unroll
    for (int i = 0; i < 2; i++)
        #pragma unroll
        for (int j = 0; j < 8; j++)
            #pragma unroll
            for (int q = 0; q < 4; q++) acc[i][j][q] = 0.f;

    auto load_stage = [&](int c) {
        int s = c % 3;
        #pragma unroll
        for (int p = 0; p < 4; p++) {
            int idx = tid + p * 256;
            int r = idx >> 3, c16 = idx & 7;
            cpa16(s2u(&As[s][r][c16 * 4]), &A[(size_t)(row0 + r) * 1024 + c * 32 + c16 * 4]);
            cpa16(s2u(&Bs[s][r][c16 * 4]), &Bt[(size_t)(col0 + r) * 1024 + c * 32 + c16 * 4]);
        }
        cpcommit();
    };

    auto mma_half = [&](int s, int k8base) {
        #pragma unroll
        for (int k8 = 0; k8 < 16; k8 += 8) {
            int kk = k8base + k8;
            uint32_t a[2][4];
            #pragma unroll
            for (int i = 0; i < 2; i++)
                ldsm4(a[i][0], a[i][1], a[i][2], a[i][3],
                      s2u(&As[s][warpm * 32 + i * 16 + aro][kk + aco]));
            #pragma unroll
            for (int jp = 0; jp < 4; jp++) {
                uint32_t b0, b1, b2, b3;
                ldsm4(b0, b1, b2, b3,
                      s2u(&Bs[s][warpn * 64 + jp * 16 + bro][kk + bco]));
                uint32_t bj0[2] = {b0, b1}, bj1[2] = {b2, b3};
                #pragma unroll
                for (int i = 0; i < 2; i++) {
                    mma8(acc[i][jp * 2 + 0], a[i], bj0);
                    mma8(acc[i][jp * 2 + 1], a[i], bj1);
                }
            }
        }
    };

    load_stage(0); load_stage(1);

    for (int c = 0; c < 32; c++) {
        int s = c % 3;
        if (c < 31) cpwait<1>(); else cpwait<0>();
        __syncthreads();

        mma_half(s, 0);
        if (c + 2 < 32) load_stage(c + 2);
        mma_half(s, 16);
    }

    #pragma unroll
    for (int i = 0; i < 2; i++) {
        #pragma unroll
        for (int half = 0; half < 2; half++) {
            int m = row0 + warpm * 32 + i * 16 + gr + half * 8;
            #pragma unroll
            for (int j = 0; j < 8; j++) {
                int col = col0 + warpn * 64 + j * 8 + 2 * tq;
                float v0 = acc[i][j][half * 2 + 0] + __ldg(&bias[col]);
                float v1 = acc[i][j][half * 2 + 1] + __ldg(&bias[col + 1]);
                if (MODE == 1) {
                    *(float2*)&Cout[(size_t)m * 1024 + col] = make_float2(v0, v1);
                } else {
                    int which = col >> 10;
                    int d = col & 1023, h = d >> 6, dd = d & 63;
                    int b = m >> 11, t = m & 2047;
                    if (which != 2) { v0 = f2tf(v0); v1 = f2tf(v1); }
                    float* dst = (which == 0) ? g_q : (which == 1) ? g_k : g_v;
                    *(float2*)&dst[((size_t)(b * NH + h) * T_ + t) * HD + dd] =
                        make_float2(v0, v1);
                }
            }
        }
    }
}

// ======================= kernel A: rowsums only (R14) ========================
__global__ void __launch_bounds__(256, 2) attn_rowsum() {
    extern __shared__ float sm[];
    float* Qs = sm;                 // [128][68]
    float* Ks = sm + 128 * 68;      // [2][128][68]

    int tid = threadIdx.x, wid = tid >> 5, lane = tid & 31;
    int gr = lane >> 2, tq = lane & 3;
    int warpm = wid & 3, warpn = wid >> 2;
    int r0 = blockIdx.x * 128, bh = blockIdx.y;

    int g8 = lane >> 3, lr = lane & 7;
    int aro = (g8 & 1) * 8 + lr, aco = (g8 >> 1) * 4;
    int bro = (g8 >> 1) * 8 + lr, bco = (g8 & 1) * 4;

    const float* qh = g_q + ((size_t)bh * T_ + r0) * HD;
    const float* kh = g_k + (size_t)bh * T_ * HD;

    auto loadK = [&](int c) {
        float* dst = Ks + (size_t)(c & 1) * 128 * 68;
        #pragma unroll
        for (int p = 0; p < 8; p++) {
            int idx = tid + p * 256;
            int r = idx >> 4, c4 = idx & 15;
            cpa16(s2u(&dst[r * 68 + c4 * 4]), kh + (size_t)(c * 128 + r) * HD + c4 * 4);
        }
        cpcommit();
    };

    #pragma unroll
    for (int p = 0; p < 8; p++) {
        int idx = tid + p * 256;
        int r = idx >> 4, c4 = idx & 15;
        cpa16(s2u(&Qs[r * 68 + c4 * 4]), qh + (size_t)r * HD + c4 * 4);
    }
    {
        float* dst = Ks;
        #pragma unroll
        for (int p = 0; p < 8; p++) {
            int idx = tid + p * 256;
            int r = idx >> 4, c4 = idx & 15;
            cpa16(s2u(&dst[r * 68 + c4 * 4]), kh + (size_t)r * HD + c4 * 4);
        }
    }
    cpcommit();
    loadK(1);

    float sums[2][2] = {{0.f, 0.f}, {0.f, 0.f}};

    for (int c = 0; c < 16; c++) {
        if (c < 15) cpwait<1>(); else cpwait<0>();
        __syncthreads();
        const float* Kb = Ks + (size_t)(c & 1) * 128 * 68;

        float acc[2][8][4];
        #pragma unroll
        for (int i = 0; i < 2; i++)
            #pragma unroll
            for (int j = 0; j < 8; j++)
                #pragma unroll
                for (int q = 0; q < 4; q++) acc[i][j][q] = 0.f;

        #pragma unroll
        for (int k8 = 0; k8 < 64; k8 += 8) {
            uint32_t a[2][4];
            #pragma unroll
            for (int i = 0; i < 2; i++)
                ldsm4(a[i][0], a[i][1], a[i][2], a[i][3],
                      s2u(&Qs[(warpm * 32 + i * 16 + aro) * 68 + k8 + aco]));
            #pragma unroll
            for (int jp = 0; jp < 4; jp++) {
                uint32_t b0, b1, b2, b3;
                ldsm4(b0, b1, b2, b3,
                      s2u(&Kb[(warpn * 64 + jp * 16 + bro) * 68 + k8 + bco]));
                uint32_t bj0[2] = {b0, b1}, bj1[2] = {b2, b3};
                #pragma unroll
                for (int i = 0; i < 2; i++) {
                    mma8(acc[i][jp * 2 + 0], a[i], bj0);
                    mma8(acc[i][jp * 2 + 1], a[i], bj1);
                }
            }
        }

        #pragma unroll
        for (int i = 0; i < 2; i++)
            #pragma unroll
            for (int half = 0; half < 2; half++) {
                float s = 0.f;
                #pragma unroll
                for (int j = 0; j < 8; j++) {
                    s += __expf(0.125f * acc[i][j][half * 2 + 0]);
                    s += __expf(0.125f * acc[i][j][half * 2 + 1]);
                }
                sums[i][half] += s;
            }

        __syncthreads();
        if (c + 2 < 16) loadK(c + 2);
    }

    #pragma unroll
    for (int i = 0; i < 2; i++)
        #pragma unroll
        for (int half = 0; half < 2; half++) {
            float s = sums[i][half];
            s += __shfl_xor_sync(0xffffffffu, s, 1);
            s += __shfl_xor_sync(0xffffffffu, s, 2);
            if (tq == 0) {
                int r = r0 + warpm * 32 + i * 16 + gr + half * 8;
                atomicAdd(&g_rowsum[(size_t)bh * T_ + r], s);
            }
        }
}

// ======================= kernel B: fused W-write + O (R14) ==================
#define ESS 132
#define FB_QS   0
#define FB_KS   (128 * 68)
#define FB_ES   (FB_KS + 2 * 128 * 68)
#define FB_VS   (FB_ES + 128 * ESS)
#define FB_INV  (FB_VS + 64 * 132)
#define FB_FLTS (FB_INV + 128)

__global__ void __launch_bounds__(256, 1) attn_fused(float* __restrict__ wts) {
    extern __shared__ float sm[];
    float* Qs  = sm + FB_QS;
    float* Ks  = sm + FB_KS;
    float* Es  = sm + FB_ES;
    float* Vs  = sm + FB_VS;
    float* inv = sm + FB_INV;

    int tid = threadIdx.x, wid = tid >> 5, lane = tid & 31;
    int gr = lane >> 2, tq = lane & 3;
    int warpm = wid & 3, warpn = wid >> 2;
    int r0 = blockIdx.x * 128, bh = blockIdx.y;

    int g8 = lane >> 3, lr = lane & 7;
    int aro = (g8 & 1) * 8 + lr, aco = (g8 >> 1) * 4;
    int bro = (g8 >> 1) * 8 + lr, bco = (g8 & 1) * 4;

    const float* qh  = g_q  + ((size_t)bh * T_ + r0) * HD;
    const float* kh  = g_k  + (size_t)bh * T_ * HD;
    const float* vtb = g_vt + (size_t)bh * HD * T_;
    float* wbase = wts + ((size_t)bh * T_ + r0) * T_;

    if (tid < 128) inv[tid] = 1.f / g_rowsum[(size_t)bh * T_ + r0 + tid];

    auto loadK = [&](int c) {
        float* dst = Ks + (size_t)(c & 1) * 128 * 68;
        #pragma unroll
        for (int p = 0; p < 8; p++) {
            int idx = tid + p * 256;
            int r = idx >> 4, c4 = idx & 15;
            cpa16(s2u(&dst[r * 68 + c4 * 4]), kh + (size_t)(c * 128 + r) * HD + c4 * 4);
        }
        cpcommit();
    };
    auto loadV = [&](int c) {
        #pragma unroll
        for (int p = 0; p < 8; p++) {
            int idx = tid + p * 256;
            int r = idx >> 5, c4 = idx & 31;
            cpa16(s2u(&Vs[r * 132 + c4 * 4]), vtb + (size_t)r * T_ + c * 128 + c4 * 4);
        }
        cpcommit();
    };

    #pragma unroll
    for (int p = 0; p < 8; p++) {
        int idx = tid + p * 256;
        int r = idx >> 4, c4 = idx & 15;
        cpa16(s2u(&Qs[r * 68 + c4 * 4]), qh + (size_t)r * HD + c4 * 4);
    }
    {
        float* dst = Ks;
        #pragma unroll
        for (int p = 0; p < 8; p++) {
            int idx = tid + p * 256;
            int r = idx >> 4, c4 = idx & 15;
            cpa16(s2u(&dst[r * 68 + c4 * 4]), kh + (size_t)r * HD + c4 * 4);
        }
    }
    cpcommit();

    float acco[2][4][4];
    #pragma unroll
    for (int i = 0; i < 2; i++)
        #pragma unroll
        for (int j = 0; j < 4; j++)
            #pragma unroll
            for (int q = 0; q < 4; q++) acco[i][j][q] = 0.f;

    for (int c = 0; c < 16; c++) {
        cpwait<0>();
        __syncthreads();             // Ks[c] visible; Es/Vs free; inv ready
        loadV(c);
        if (c < 15) loadK(c + 1);

        const float* Kb = Ks + (size_t)(c & 1) * 128 * 68;

        // ---- QK^T ----
        float acc[2][8][4];
        #pragma unroll
        for (int i = 0; i < 2; i++)
            #pragma unroll
            for (int j = 0; j < 8; j++)
                #pragma unroll
                for (int q = 0; q < 4; q++) acc[i][j][q] = 0.f;

        #pragma unroll
        for (int k8 = 0; k8 < 64; k8 += 8) {
            uint32_t a[2][4];
            #pragma unroll
            for (int i = 0; i < 2; i++)
                ldsm4(a[i][0], a[i][1], a[i][2], a[i][3],
                      s2u(&Qs[(warpm * 32 + i * 16 + aro) * 68 + k8 + aco]));
            #pragma unroll
            for (int jp = 0; jp < 4; jp++) {
                uint32_t b0, b1, b2, b3;
                ldsm4(b0, b1, b2, b3,
                      s2u(&Kb[(warpn * 64 + jp * 16 + bro) * 68 + k8 + bco]));
                uint32_t bj0[2] = {b0, b1}, bj1[2] = {b2, b3};
                #pragma unroll
                for (int i = 0; i < 2; i++) {
                    mma8(acc[i][jp * 2 + 0], a[i], bj0);
                    mma8(acc[i][jp * 2 + 1], a[i], bj1);
                }
            }
        }

        // ---- w = exp*inv -> Es ----
        #pragma unroll
        for (int i = 0; i < 2; i++) {
            #pragma unroll
            for (int half = 0; half < 2; half++) {
                int lrw = warpm * 32 + i * 16 + gr + half * 8;
                float iv = inv[lrw];
                #pragma unroll
                for (int j = 0; j < 8; j++) {
                    int col = warpn * 64 + j * 8 + 2 * tq;
                    float w0 = __expf(0.125f * acc[i][j][half * 2 + 0]) * iv;
                    float w1 = __expf(0.125f * acc[i][j][half * 2 + 1]) * iv;
                    *(float2*)&Es[lrw * ESS + col] = make_float2(w0, w1);
                }
            }
        }

        if (c < 15) cpwait<1>(); else cpwait<0>();   // V[c] arrived
        __syncthreads();                              // Es + Vs visible

        // ---- coalesced W store ----
        #pragma unroll
        for (int rr = 0; rr < 16; rr++) {
            int row = wid * 16 + rr;
            float4 v = *(float4*)&Es[row * ESS + lane * 4];
            *(float4*)&wbase[(size_t)row * T_ + c * 128 + lane * 4] = v;
        }

        // ---- O += Es @ V ----
        #pragma unroll
        for (int k8 = 0; k8 < 128; k8 += 8) {
            uint32_t a[2][4];
            #pragma unroll
            for (int i = 0; i < 2; i++)
                ldsm4(a[i][0], a[i][1], a[i][2], a[i][3],
                      s2u(&Es[(warpm * 32 + i * 16 + aro) * ESS + k8 + aco]));
            #pragma unroll
            for (int jp = 0; jp < 2; jp++) {
                uint32_t b0, b1, b2, b3;
                ldsm4(b0, b1, b2, b3,
                      s2u(&Vs[(warpn * 32 + jp * 16 + bro) * 132 + k8 + bco]));
                uint32_t bj0[2] = {b0, b1}, bj1[2] = {b2, b3};
                #pragma unroll
                for (int i = 0; i < 2; i++) {
                    mma8(acco[i][jp * 2 + 0], a[i], bj0);
                    mma8(acco[i][jp * 2 + 1], a[i], bj1);
                }
            }
        }
    }

    // ---- epilogue: O -> g_ao (tf32) ----
    int b = bh >> 4, h = bh & 15;
    #pragma unroll
    for (int i = 0; i < 2; i++) {
        #pragma unroll
        for (int half = 0; half < 2; half++) {
            int t = r0 + warpm * 32 + i * 16 + gr + half * 8;
            float* orow = g_ao + (size_t)(b * T_ + t) * D_MODEL + h * HD;
            #pragma unroll
            for (int j = 0; j < 4; j++) {
                int dd = warpn * 32 + j * 8 + 2 * tq;
                *(float2*)&orow[dd] = make_float2(
                    f2tf(acco[i][j][half * 2 + 0]), f2tf(acco[i][j][half * 2 + 1]));
            }
        }
    }
}

// ===========================================================================
extern "C" void kernel_launch(void* const* d_in, const int* in_sizes, int n_in,
                              void* d_out, int out_size) {
    const float* x    = (const float*)d_in[0];
    const float* Wqkv = (const float*)d_in[1];
    const float* bqkv = (const float*)d_in[2];
    const float* Wo   = (const float*)d_in[3];
    const float* bo   = (const float*)d_in[4];

    float* y   = (float*)d_out;                         // [B,T,D]
    float* wts = (float*)d_out + (size_t)BT * D_MODEL;  // [B,H,T,T]

    const int GB_SMEM = 2 * 3 * 128 * GBS * 4;          // 110592
    const int RS_SMEM = 3 * 128 * 68 * 4;               // 104448
    const int FB_SMEM = FB_FLTS * 4;
    cudaFuncSetAttribute(gemm_big<0>, cudaFuncAttributeMaxDynamicSharedMemorySize, GB_SMEM);
    cudaFuncSetAttribute(gemm_big<1>, cudaFuncAttributeMaxDynamicSharedMemorySize, GB_SMEM);
    cudaFuncSetAttribute(attn_rowsum, cudaFuncAttributeMaxDynamicSharedMemorySize, RS_SMEM);
    cudaFuncSetAttribute(attn_fused,  cudaFuncAttributeMaxDynamicSharedMemorySize, FB_SMEM);

    float *wt_p = nullptr, *wot_p = nullptr, *ao_p = nullptr;
    cudaGetSymbolAddress((void**)&wt_p,  g_wt);
    cudaGetSymbolAddress((void**)&wot_p, g_wot);
    cudaGetSymbolAddress((void**)&ao_p,  g_ao);

    zero_rowsum2<<<BH * T_ / 256, 256>>>();
    transpose_w2<<<dim3(96, 32, 2), dim3(32, 8)>>>(Wqkv, Wo, wt_p, wot_p);

    // QKV GEMM reads raw x (fp32 bits truncated to tf32 by the mma)
    gemm_big<0><<<dim3(24, 32), 256, GB_SMEM>>>(x, wt_p, bqkv, nullptr);
    transpose_v<<<dim3(2, 64, 32), dim3(32, 8)>>>();

    attn_rowsum<<<dim3(16, 32), 256, RS_SMEM>>>();
    attn_fused<<<dim3(16, 32), 256, FB_SMEM>>>(wts);

    gemm_big<1><<<dim3(8, 32), 256, GB_SMEM>>>(ao_p, wot_p, bo, y);
}